// round 14
// baseline (speedup 1.0000x reference)
#include <cuda_runtime.h>
#include <cuda_fp16.h>
#include <cstdint>

// Problem sizes
#define NROW 2048   // B*DEPTH = 16*128
#define NK   1024   // HID
#define NC   2048   // DIN == DOUT
#define B_   16

// ---------------------------------------------------------------------------
// fp16 hi/lo split scratch (device globals, 16B-aligned for cp.async/vector IO)
// ---------------------------------------------------------------------------
__device__ __align__(256) __half g_Lhi[NROW * NK], g_Llo[NROW * NK];      // logits split
__device__ __align__(256) __half g_Wthi[2][NC * NK], g_Wtlo[2][NC * NK];  // W^T split
__device__ __align__(256) __half g_Vhi[2][NROW * NC], g_Vlo[2][NROW * NC];// iv(0)/ov(1)

// ---------------------------------------------------------------------------
// helpers (all plain sm_80-era PTX — valid at target compute_103)
// ---------------------------------------------------------------------------
__device__ __forceinline__ uint32_t smem_to_u32(const void* p) {
    uint32_t a;
    asm("{ .reg .u64 t; cvta.to.shared.u64 t, %1; cvt.u32.u64 %0, t; }" : "=r"(a) : "l"(p));
    return a;
}

#define CPA16(s, g) \
    asm volatile("cp.async.cg.shared.global [%0], [%1], 16;" :: "r"(s), "l"(g))
#define CPCOMMIT() asm volatile("cp.async.commit_group;")
#define CPWAIT(n)  asm volatile("cp.async.wait_group %0;" :: "n"(n))

#define LDSM4(r0, r1, r2, r3, a) \
    asm volatile("ldmatrix.sync.aligned.m8n8.x4.shared.b16 {%0,%1,%2,%3}, [%4];" \
                 : "=r"(r0), "=r"(r1), "=r"(r2), "=r"(r3) : "r"(a))
#define LDSM4T(r0, r1, r2, r3, a) \
    asm volatile("ldmatrix.sync.aligned.m8n8.x4.trans.shared.b16 {%0,%1,%2,%3}, [%4];" \
                 : "=r"(r0), "=r"(r1), "=r"(r2), "=r"(r3) : "r"(a))

// fp32-accum MMA (hh term)
#define MMA(c, a, b) \
    asm volatile("mma.sync.aligned.m16n8k16.row.col.f32.f16.f16.f32 " \
                 "{%0,%1,%2,%3},{%4,%5,%6,%7},{%8,%9},{%0,%1,%2,%3};" \
                 : "+f"((c)[0]), "+f"((c)[1]), "+f"((c)[2]), "+f"((c)[3]) \
                 : "r"((a)[0]), "r"((a)[1]), "r"((a)[2]), "r"((a)[3]), \
                   "r"((b)[0]), "r"((b)[1]))

// fp16-accum MMA (hl/lh correction terms — small-valued, fp16 precision ample)
#define MMAH(c, a, b) \
    asm volatile("mma.sync.aligned.m16n8k16.row.col.f16.f16.f16.f16 " \
                 "{%0,%1},{%2,%3,%4,%5},{%6,%7},{%0,%1};" \
                 : "+r"((c)[0]), "+r"((c)[1]) \
                 : "r"((a)[0]), "r"((a)[1]), "r"((a)[2]), "r"((a)[3]), \
                   "r"((b)[0]), "r"((b)[1]))

__device__ __forceinline__ float clamp5(float v) {
    return fminf(fmaxf(v, -5.0f), 5.0f);
}

// ---------------------------------------------------------------------------
// Prep 1: split logits fp32 -> fp16 hi/lo (same [row][k] layout)
// ---------------------------------------------------------------------------
__global__ void k_split(const float* __restrict__ X) {
    int i = blockIdx.x * blockDim.x + threadIdx.x;   // one float4 each
    if (i >= NROW * NK / 4) return;
    float4 v = reinterpret_cast<const float4*>(X)[i];
    __half h0 = __float2half_rn(v.x), h1 = __float2half_rn(v.y);
    __half h2 = __float2half_rn(v.z), h3 = __float2half_rn(v.w);
    __half2* H = reinterpret_cast<__half2*>(g_Lhi);
    __half2* L = reinterpret_cast<__half2*>(g_Llo);
    H[2 * i]     = __halves2half2(h0, h1);
    H[2 * i + 1] = __halves2half2(h2, h3);
    L[2 * i]     = __halves2half2(__float2half_rn(v.x - __half2float(h0)),
                                  __float2half_rn(v.y - __half2float(h1)));
    L[2 * i + 1] = __halves2half2(__float2half_rn(v.z - __half2float(h2)),
                                  __float2half_rn(v.w - __half2float(h3)));
}

// ---------------------------------------------------------------------------
// Prep 2: transpose + split W [1024 hid][2048 col] -> Wt[which] [col][hid]
// ---------------------------------------------------------------------------
__global__ void k_wtrans(const float* __restrict__ W, int which) {
    __shared__ float t[32][33];
    const int c0 = blockIdx.x * 32, h0 = blockIdx.y * 32;
    const int tx = threadIdx.x, ty = threadIdx.y;    // 32 x 8
#pragma unroll
    for (int j = 0; j < 4; j++)
        t[ty + j * 8][tx] = W[(size_t)(h0 + ty + j * 8) * NC + c0 + tx];
    __syncthreads();
    __half* hi = g_Wthi[which];
    __half* lo = g_Wtlo[which];
#pragma unroll
    for (int j = 0; j < 4; j++) {
        float v = t[tx][ty + j * 8];
        __half h = __float2half_rn(v);
        size_t off = (size_t)(c0 + ty + j * 8) * NK + h0 + tx;
        hi[off] = h;
        lo[off] = __float2half_rn(v - __half2float(h));
    }
}

// ===========================================================================
// Phase 1: V[z] = clamp(L @ Wt[z]^T + bias[z]).  M=2048, N=2048, K=1024.
// Block 128x128, BK=32, 8 warps (4m x 2n), 2-stage cp.async ring (R11 base).
// hh -> fp32-accum MMA; hl+lh -> shared fp16-accum MMA (half the fp32-acc ops).
// SMEM stage: Ah|Al|Bh|Bl planes of [128][40] halves (pad 8) = 10240B each.
// ===========================================================================
#define P1_STAGE 40960
#define P1_PLANE 10240

__global__ __launch_bounds__(256, 1)
void k_gen(const float* __restrict__ bi, const float* __restrict__ bo)
{
    extern __shared__ char smem[];
    const uint32_t sbase = smem_to_u32(smem);
    const int tid = threadIdx.x, lane = tid & 31, wid = tid >> 5;
    const int wm = wid & 3, wn = wid >> 2;
    const int row0 = blockIdx.y * 128, col0 = blockIdx.x * 128;
    const int z = blockIdx.z;

    const __half* __restrict__ pAh = g_Lhi + (size_t)row0 * NK;
    const __half* __restrict__ pAl = g_Llo + (size_t)row0 * NK;
    const __half* __restrict__ pBh = g_Wthi[z] + (size_t)col0 * NK;
    const __half* __restrict__ pBl = g_Wtlo[z] + (size_t)col0 * NK;

    float acc[2][8][4];
    uint32_t acch[2][8][2];          // fp16x2 correction accumulators
#pragma unroll
    for (int mi = 0; mi < 2; mi++)
#pragma unroll
        for (int ni = 0; ni < 8; ni++) {
#pragma unroll
            for (int q = 0; q < 4; q++) acc[mi][ni][q] = 0.0f;
            acch[mi][ni][0] = 0u; acch[mi][ni][1] = 0u;
        }

#define GEN_LOAD(s_, st_) do {                                                  \
    const int k0_ = (s_) * 32;                                                  \
    const uint32_t d0_ = sbase + (uint32_t)(st_) * P1_STAGE;                    \
    _Pragma("unroll")                                                           \
    for (int i_ = 0; i_ < 8; i_++) {                                            \
        const int p_ = i_ >> 1;                                                 \
        const int cc_ = tid + (i_ & 1) * 256;                                   \
        const int row_ = cc_ >> 2, kc_ = cc_ & 3;                               \
        const uint32_t d_ = d0_ + p_ * P1_PLANE + row_ * 80 + kc_ * 16;         \
        const __half* g_ =                                                      \
            (p_ == 0 ? pAh : p_ == 1 ? pAl : p_ == 2 ? pBh : pBl)               \
            + (size_t)row_ * NK + k0_ + kc_ * 8;                                \
        CPA16(d_, g_);                                                          \
    }                                                                           \
    CPCOMMIT();                                                                 \
} while (0)

#define GEN_COMP(st_) do {                                                      \
    const uint32_t sb_ = sbase + (uint32_t)(st_) * P1_STAGE;                    \
    _Pragma("unroll")                                                           \
    for (int ks = 0; ks < 2; ks++) {                                            \
        uint32_t ah[2][4], al[2][4];                                            \
        _Pragma("unroll")                                                       \
        for (int mi = 0; mi < 2; mi++) {                                        \
            uint32_t ra = sb_ + ((wm * 32 + mi * 16 + (lane & 15)) * 40         \
                                 + ks * 16 + ((lane >> 4) << 3)) * 2;           \
            LDSM4(ah[mi][0], ah[mi][1], ah[mi][2], ah[mi][3], ra);              \
            LDSM4(al[mi][0], al[mi][1], al[mi][2], al[mi][3], ra + P1_PLANE);   \
        }                                                                       \
        _Pragma("unroll")                                                       \
        for (int ng = 0; ng < 4; ng++) {                                        \
            uint32_t bh[2][2], bl[2][2];                                        \
            uint32_t rb = sb_ + 2 * P1_PLANE                                    \
                + ((wn * 64 + ng * 16 + ((lane >> 4) << 3) + (lane & 7)) * 40   \
                   + ks * 16 + (((lane >> 3) & 1) << 3)) * 2;                   \
            LDSM4(bh[0][0], bh[0][1], bh[1][0], bh[1][1], rb);                  \
            LDSM4(bl[0][0], bl[0][1], bl[1][0], bl[1][1], rb + P1_PLANE);       \
            _Pragma("unroll")                                                   \
            for (int mi = 0; mi < 2; mi++)                                      \
                _Pragma("unroll")                                               \
                for (int nn = 0; nn < 2; nn++) {                                \
                    MMA(acc[mi][2 * ng + nn], ah[mi], bh[nn]);                  \
                    MMAH(acch[mi][2 * ng + nn], ah[mi], bl[nn]);                \
                    MMAH(acch[mi][2 * ng + nn], al[mi], bh[nn]);                \
                }                                                               \
        }                                                                       \
    }                                                                           \
} while (0)

    GEN_LOAD(0, 0);
    for (int s = 0; s < 32; s++) {
        if (s + 1 < 32) { GEN_LOAD(s + 1, (s + 1) & 1); CPWAIT(1); }
        else            { CPWAIT(0); }
        __syncthreads();
        GEN_COMP(s & 1);
        __syncthreads();
    }

    // epilogue: merge fp16 corrections, +bias, clamp, fp16 split, store
    const float* __restrict__ bias = z ? bo : bi;
    __half* __restrict__ Oh = g_Vhi[z];
    __half* __restrict__ Ol = g_Vlo[z];
#pragma unroll
    for (int mi = 0; mi < 2; mi++)
#pragma unroll
        for (int ni = 0; ni < 8; ni++) {
            int rr = row0 + wm * 32 + mi * 16 + (lane >> 2);
            int gc = col0 + wn * 64 + ni * 8 + (lane & 3) * 2;
            float b0v = __ldg(bias + gc), b1v = __ldg(bias + gc + 1);
            __half2 hc0 = *reinterpret_cast<__half2*>(&acch[mi][ni][0]);
            __half2 hc1 = *reinterpret_cast<__half2*>(&acch[mi][ni][1]);

            float v0 = clamp5(acc[mi][ni][0] + __low2float(hc0) + b0v);
            float v1 = clamp5(acc[mi][ni][1] + __high2float(hc0) + b1v);
            __half h0 = __float2half_rn(v0), h1 = __float2half_rn(v1);
            *(__half2*)(Oh + (size_t)rr * NC + gc) = __halves2half2(h0, h1);
            *(__half2*)(Ol + (size_t)rr * NC + gc) =
                __halves2half2(__float2half_rn(v0 - __half2float(h0)),
                               __float2half_rn(v1 - __half2float(h1)));

            float v2 = clamp5(acc[mi][ni][2] + __low2float(hc1) + b0v);
            float v3 = clamp5(acc[mi][ni][3] + __high2float(hc1) + b1v);
            __half h2 = __float2half_rn(v2), h3 = __float2half_rn(v3);
            *(__half2*)(Oh + (size_t)(rr + 8) * NC + gc) = __halves2half2(h2, h3);
            *(__half2*)(Ol + (size_t)(rr + 8) * NC + gc) =
                __halves2half2(__float2half_rn(v2 - __half2float(h2)),
                               __float2half_rn(v3 - __half2float(h3)));
        }
#undef GEN_LOAD
#undef GEN_COMP
}

// ===========================================================================
// Phase 2: out[b] = wp[b] + iv[b]^T @ ov[b].  Per batch M=N=2048, K=128.
// 2-stage ring (69632B smem), same fp16-accum correction scheme.
// SMEM stage: Ah|Al|Bh|Bl planes of [32 d][136] halves (pad 8) = 8704B each.
// ===========================================================================
#define P2_STAGE   34816
#define P2_PLANE   8704

__global__ __launch_bounds__(256, 1)
void k_outer(const float* __restrict__ wp, float* __restrict__ out)
{
    extern __shared__ char smem[];
    const uint32_t sbase = smem_to_u32(smem);
    const int tid = threadIdx.x, lane = tid & 31, wid = tid >> 5;
    const int wm = wid & 3, wn = wid >> 2;
    const int b = blockIdx.z;
    const int i0 = blockIdx.y * 128, j0 = blockIdx.x * 128;

    const __half* __restrict__ pAh = g_Vhi[0] + (size_t)(b * 128) * NC + i0;
    const __half* __restrict__ pAl = g_Vlo[0] + (size_t)(b * 128) * NC + i0;
    const __half* __restrict__ pBh = g_Vhi[1] + (size_t)(b * 128) * NC + j0;
    const __half* __restrict__ pBl = g_Vlo[1] + (size_t)(b * 128) * NC + j0;

    float acc[2][8][4];
    uint32_t acch[2][8][2];
#pragma unroll
    for (int mi = 0; mi < 2; mi++)
#pragma unroll
        for (int ni = 0; ni < 8; ni++) {
#pragma unroll
            for (int q = 0; q < 4; q++) acc[mi][ni][q] = 0.0f;
            acch[mi][ni][0] = 0u; acch[mi][ni][1] = 0u;
        }

#define OUT_LOAD(s_, st_) do {                                                  \
    const int d0_ = (s_) * 32;                                                  \
    const uint32_t b0_ = sbase + (uint32_t)(st_) * P2_STAGE;                    \
    _Pragma("unroll")                                                           \
    for (int i_ = 0; i_ < 8; i_++) {                                            \
        const int p_ = i_ >> 1;                                                 \
        const int cc_ = tid + (i_ & 1) * 256;                                   \
        const int row_ = cc_ >> 4, ch_ = cc_ & 15;                              \
        const uint32_t d_ = b0_ + p_ * P2_PLANE + row_ * 272 + ch_ * 16;        \
        const __half* g_ =                                                      \
            (p_ == 0 ? pAh : p_ == 1 ? pAl : p_ == 2 ? pBh : pBl)               \
            + (size_t)(d0_ + row_) * NC + ch_ * 8;                              \
        CPA16(d_, g_);                                                          \
    }                                                                           \
    CPCOMMIT();                                                                 \
} while (0)

#define OUT_COMP(st_) do {                                                      \
    const uint32_t sb_ = sbase + (uint32_t)(st_) * P2_STAGE;                    \
    _Pragma("unroll")                                                           \
    for (int ks = 0; ks < 2; ks++) {                                            \
        uint32_t ah[2][4], al[2][4];                                            \
        _Pragma("unroll")                                                       \
        for (int mi = 0; mi < 2; mi++) {                                        \
            uint32_t ra = sb_                                                   \
                + ((ks * 16 + ((lane >> 4) << 3) + (lane & 7)) * 136            \
                   + wm * 32 + mi * 16 + (((lane >> 3) & 1) << 3)) * 2;         \
            LDSM4T(ah[mi][0], ah[mi][1], ah[mi][2], ah[mi][3], ra);             \
            LDSM4T(al[mi][0], al[mi][1], al[mi][2], al[mi][3], ra + P2_PLANE);  \
        }                                                                       \
        _Pragma("unroll")                                                       \
        for (int ng = 0; ng < 4; ng++) {                                        \
            uint32_t bh[2][2], bl[2][2];                                        \
            uint32_t rb = sb_ + 2 * P2_PLANE                                    \
                + ((ks * 16 + (((lane >> 3) & 1) << 3) + (lane & 7)) * 136      \
                   + wn * 64 + ng * 16 + ((lane >> 4) << 3)) * 2;               \
            LDSM4T(bh[0][0], bh[0][1], bh[1][0], bh[1][1], rb);                 \
            LDSM4T(bl[0][0], bl[0][1], bl[1][0], bl[1][1], rb + P2_PLANE);      \
            _Pragma("unroll")                                                   \
            for (int mi = 0; mi < 2; mi++)                                      \
                _Pragma("unroll")                                               \
                for (int nn = 0; nn < 2; nn++) {                                \
                    MMA(acc[mi][2 * ng + nn], ah[mi], bh[nn]);                  \
                    MMAH(acch[mi][2 * ng + nn], ah[mi], bl[nn]);                \
                    MMAH(acch[mi][2 * ng + nn], al[mi], bh[nn]);                \
                }                                                               \
        }                                                                       \
    }                                                                           \
} while (0)

    OUT_LOAD(0, 0);
    for (int s = 0; s < 4; s++) {
        if (s + 1 < 4) { OUT_LOAD(s + 1, (s + 1) & 1); CPWAIT(1); }
        else           { CPWAIT(0); }
        __syncthreads();
        OUT_COMP(s & 1);
        __syncthreads();
    }

    // epilogue: merge fp16 corrections, + weight_params, fp32 store
#pragma unroll
    for (int mi = 0; mi < 2; mi++)
#pragma unroll
        for (int ni = 0; ni < 8; ni++) {
            int rr = i0 + wm * 32 + mi * 16 + (lane >> 2);
            int cc = j0 + wn * 64 + ni * 8 + (lane & 3) * 2;
            size_t g0 = ((size_t)b * NC + rr) * NC + cc;
            size_t g1 = g0 + (size_t)8 * NC;
            float2 w0 = *(const float2*)(wp + g0);
            float2 w1 = *(const float2*)(wp + g1);
            __half2 hc0 = *reinterpret_cast<__half2*>(&acch[mi][ni][0]);
            __half2 hc1 = *reinterpret_cast<__half2*>(&acch[mi][ni][1]);
            *(float2*)(out + g0) =
                make_float2(acc[mi][ni][0] + __low2float(hc0) + w0.x,
                            acc[mi][ni][1] + __high2float(hc0) + w0.y);
            *(float2*)(out + g1) =
                make_float2(acc[mi][ni][2] + __low2float(hc1) + w1.x,
                            acc[mi][ni][3] + __high2float(hc1) + w1.y);
        }
#undef OUT_LOAD
#undef OUT_COMP
}

// ---------------------------------------------------------------------------
// Launch
// ---------------------------------------------------------------------------
extern "C" void kernel_launch(void* const* d_in, const int* in_sizes, int n_in,
                              void* d_out, int out_size)
{
    const float* wp = (const float*)d_in[0];  // [16, 2048, 2048]
    const float* lg = (const float*)d_in[1];  // [16, 128, 1024]
    const float* Wi = (const float*)d_in[2];  // [1024, 2048]
    const float* bi = (const float*)d_in[3];  // [2048]
    const float* Wo = (const float*)d_in[4];  // [1024, 2048]
    const float* bo = (const float*)d_in[5];  // [2048]
    float* out = (float*)d_out;               // [16, 2048, 2048]

    cudaFuncSetAttribute(k_gen,
        cudaFuncAttributeMaxDynamicSharedMemorySize, 2 * P1_STAGE);
    cudaFuncSetAttribute(k_outer,
        cudaFuncAttributeMaxDynamicSharedMemorySize, 2 * P2_STAGE);

    k_split<<<(NROW * NK / 4 + 255) / 256, 256>>>(lg);
    k_wtrans<<<dim3(NC / 32, NK / 32), dim3(32, 8)>>>(Wi, 0);
    k_wtrans<<<dim3(NC / 32, NK / 32), dim3(32, 8)>>>(Wo, 1);

    k_gen<<<dim3(16, 16, 2), 256, 2 * P1_STAGE>>>(bi, bo);
    k_outer<<<dim3(16, 16, 16), 256, 2 * P2_STAGE>>>(wp, out);
}

// round 15
// speedup vs baseline: 1.1867x; 1.1867x over previous
#include <cuda_runtime.h>
#include <cuda_fp16.h>
#include <cstdint>

// Problem sizes
#define NROW 2048   // B*DEPTH = 16*128
#define NK   1024   // HID
#define NC   2048   // DIN == DOUT
#define B_   16

// ---------------------------------------------------------------------------
// fp16 hi/lo split scratch (device globals, 16B-aligned for cp.async/vector IO)
// ---------------------------------------------------------------------------
__device__ __align__(256) __half g_Lhi[NROW * NK], g_Llo[NROW * NK];      // logits split
__device__ __align__(256) __half g_Wthi[2][NC * NK], g_Wtlo[2][NC * NK];  // W^T split
__device__ __align__(256) __half g_Vhi[2][NROW * NC], g_Vlo[2][NROW * NC];// iv(0)/ov(1)

// ---------------------------------------------------------------------------
// helpers (all plain sm_80-era PTX — valid at target compute_103)
// ---------------------------------------------------------------------------
__device__ __forceinline__ uint32_t smem_to_u32(const void* p) {
    uint32_t a;
    asm("{ .reg .u64 t; cvta.to.shared.u64 t, %1; cvt.u32.u64 %0, t; }" : "=r"(a) : "l"(p));
    return a;
}

#define CPA16(s, g) \
    asm volatile("cp.async.cg.shared.global [%0], [%1], 16;" :: "r"(s), "l"(g))
#define CPCOMMIT() asm volatile("cp.async.commit_group;")
#define CPWAIT(n)  asm volatile("cp.async.wait_group %0;" :: "n"(n))

#define LDSM4(r0, r1, r2, r3, a) \
    asm volatile("ldmatrix.sync.aligned.m8n8.x4.shared.b16 {%0,%1,%2,%3}, [%4];" \
                 : "=r"(r0), "=r"(r1), "=r"(r2), "=r"(r3) : "r"(a))
#define LDSM4T(r0, r1, r2, r3, a) \
    asm volatile("ldmatrix.sync.aligned.m8n8.x4.trans.shared.b16 {%0,%1,%2,%3}, [%4];" \
                 : "=r"(r0), "=r"(r1), "=r"(r2), "=r"(r3) : "r"(a))

#define MMA(c, a, b) \
    asm volatile("mma.sync.aligned.m16n8k16.row.col.f32.f16.f16.f32 " \
                 "{%0,%1,%2,%3},{%4,%5,%6,%7},{%8,%9},{%0,%1,%2,%3};" \
                 : "+f"((c)[0]), "+f"((c)[1]), "+f"((c)[2]), "+f"((c)[3]) \
                 : "r"((a)[0]), "r"((a)[1]), "r"((a)[2]), "r"((a)[3]), \
                   "r"((b)[0]), "r"((b)[1]))

__device__ __forceinline__ float clamp5(float v) {
    return fminf(fmaxf(v, -5.0f), 5.0f);
}

// ---------------------------------------------------------------------------
// Prep 1: split logits fp32 -> fp16 hi/lo (same [row][k] layout)
// ---------------------------------------------------------------------------
__global__ void k_split(const float* __restrict__ X) {
    int i = blockIdx.x * blockDim.x + threadIdx.x;   // one float4 each
    if (i >= NROW * NK / 4) return;
    float4 v = reinterpret_cast<const float4*>(X)[i];
    __half h0 = __float2half_rn(v.x), h1 = __float2half_rn(v.y);
    __half h2 = __float2half_rn(v.z), h3 = __float2half_rn(v.w);
    __half2* H = reinterpret_cast<__half2*>(g_Lhi);
    __half2* L = reinterpret_cast<__half2*>(g_Llo);
    H[2 * i]     = __halves2half2(h0, h1);
    H[2 * i + 1] = __halves2half2(h2, h3);
    L[2 * i]     = __halves2half2(__float2half_rn(v.x - __half2float(h0)),
                                  __float2half_rn(v.y - __half2float(h1)));
    L[2 * i + 1] = __halves2half2(__float2half_rn(v.z - __half2float(h2)),
                                  __float2half_rn(v.w - __half2float(h3)));
}

// ---------------------------------------------------------------------------
// Prep 2: transpose + split W [1024 hid][2048 col] -> Wt[which] [col][hid]
// ---------------------------------------------------------------------------
__global__ void k_wtrans(const float* __restrict__ W, int which) {
    __shared__ float t[32][33];
    const int c0 = blockIdx.x * 32, h0 = blockIdx.y * 32;
    const int tx = threadIdx.x, ty = threadIdx.y;    // 32 x 8
#pragma unroll
    for (int j = 0; j < 4; j++)
        t[ty + j * 8][tx] = W[(size_t)(h0 + ty + j * 8) * NC + c0 + tx];
    __syncthreads();
    __half* hi = g_Wthi[which];
    __half* lo = g_Wtlo[which];
#pragma unroll
    for (int j = 0; j < 4; j++) {
        float v = t[tx][ty + j * 8];
        __half h = __float2half_rn(v);
        size_t off = (size_t)(c0 + ty + j * 8) * NK + h0 + tx;
        hi[off] = h;
        lo[off] = __float2half_rn(v - __half2float(h));
    }
}

// ===========================================================================
// Phase 1: V[z] = clamp(L @ Wt[z]^T + bias[z]).  M=2048, N=2048, K=1024.
// Block 128x128, BK=32, 8 warps (4m x 2n). 4-stage cp.async ring, ONE
// barrier per slab. GEN_COMP hoists ALL 16 LDSMs for the slab (96 frag regs,
// 1 CTA / 255-reg budget) then issues 96 MMAs with 16-way accumulator ILP.
// SMEM stage: Ah|Al|Bh|Bl planes of [128][40] halves (pad 8) = 10240B each.
// ===========================================================================
#define P1_STAGE 40960
#define P1_PLANE 10240

__global__ __launch_bounds__(256, 1)
void k_gen(const float* __restrict__ bi, const float* __restrict__ bo)
{
    extern __shared__ char smem[];
    const uint32_t sbase = smem_to_u32(smem);
    const int tid = threadIdx.x, lane = tid & 31, wid = tid >> 5;
    const int wm = wid & 3, wn = wid >> 2;
    const int row0 = blockIdx.y * 128, col0 = blockIdx.x * 128;
    const int z = blockIdx.z;

    const __half* __restrict__ pAh = g_Lhi + (size_t)row0 * NK;
    const __half* __restrict__ pAl = g_Llo + (size_t)row0 * NK;
    const __half* __restrict__ pBh = g_Wthi[z] + (size_t)col0 * NK;
    const __half* __restrict__ pBl = g_Wtlo[z] + (size_t)col0 * NK;

    float acc[2][8][4];
#pragma unroll
    for (int mi = 0; mi < 2; mi++)
#pragma unroll
        for (int ni = 0; ni < 8; ni++)
#pragma unroll
            for (int q = 0; q < 4; q++) acc[mi][ni][q] = 0.0f;

#define GEN_LOAD(s_, st_) do {                                                  \
    const int k0_ = (s_) * 32;                                                  \
    const uint32_t d0_ = sbase + (uint32_t)(st_) * P1_STAGE;                    \
    _Pragma("unroll")                                                           \
    for (int i_ = 0; i_ < 8; i_++) {                                            \
        const int p_ = i_ >> 1;                                                 \
        const int cc_ = tid + (i_ & 1) * 256;                                   \
        const int row_ = cc_ >> 2, kc_ = cc_ & 3;                               \
        const uint32_t d_ = d0_ + p_ * P1_PLANE + row_ * 80 + kc_ * 16;         \
        const __half* g_ =                                                      \
            (p_ == 0 ? pAh : p_ == 1 ? pAl : p_ == 2 ? pBh : pBl)               \
            + (size_t)row_ * NK + k0_ + kc_ * 8;                                \
        CPA16(d_, g_);                                                          \
    }                                                                           \
    CPCOMMIT();                                                                 \
} while (0)

// All fragment loads hoisted to the top of the slab; MMAs issued with
// mi/ni varying fastest (16 independent accumulator chains between reuses).
#define GEN_COMP(st_) do {                                                      \
    const uint32_t sb_ = sbase + (uint32_t)(st_) * P1_STAGE;                    \
    uint32_t ah[2][2][4], al[2][2][4], bh[2][8][2], bl[2][8][2];                \
    _Pragma("unroll")                                                           \
    for (int ks = 0; ks < 2; ks++) {                                            \
        _Pragma("unroll")                                                       \
        for (int mi = 0; mi < 2; mi++) {                                        \
            uint32_t ra = sb_ + ((wm * 32 + mi * 16 + (lane & 15)) * 40         \
                                 + ks * 16 + ((lane >> 4) << 3)) * 2;           \
            LDSM4(ah[ks][mi][0], ah[ks][mi][1], ah[ks][mi][2], ah[ks][mi][3],   \
                  ra);                                                          \
            LDSM4(al[ks][mi][0], al[ks][mi][1], al[ks][mi][2], al[ks][mi][3],   \
                  ra + P1_PLANE);                                               \
        }                                                                       \
        _Pragma("unroll")                                                       \
        for (int ng = 0; ng < 4; ng++) {                                        \
            uint32_t rb = sb_ + 2 * P1_PLANE                                    \
                + ((wn * 64 + ng * 16 + ((lane >> 4) << 3) + (lane & 7)) * 40   \
                   + ks * 16 + (((lane >> 3) & 1) << 3)) * 2;                   \
            LDSM4(bh[ks][2*ng][0], bh[ks][2*ng][1],                             \
                  bh[ks][2*ng+1][0], bh[ks][2*ng+1][1], rb);                    \
            LDSM4(bl[ks][2*ng][0], bl[ks][2*ng][1],                             \
                  bl[ks][2*ng+1][0], bl[ks][2*ng+1][1], rb + P1_PLANE);         \
        }                                                                       \
    }                                                                           \
    _Pragma("unroll")                                                           \
    for (int ks = 0; ks < 2; ks++) {                                            \
        _Pragma("unroll")                                                       \
        for (int mi = 0; mi < 2; mi++)                                          \
            _Pragma("unroll")                                                   \
            for (int ni = 0; ni < 8; ni++)                                      \
                MMA(acc[mi][ni], ah[ks][mi], bh[ks][ni]);                       \
        _Pragma("unroll")                                                       \
        for (int mi = 0; mi < 2; mi++)                                          \
            _Pragma("unroll")                                                   \
            for (int ni = 0; ni < 8; ni++)                                      \
                MMA(acc[mi][ni], ah[ks][mi], bl[ks][ni]);                       \
        _Pragma("unroll")                                                       \
        for (int mi = 0; mi < 2; mi++)                                          \
            _Pragma("unroll")                                                   \
            for (int ni = 0; ni < 8; ni++)                                      \
                MMA(acc[mi][ni], al[ks][mi], bh[ks][ni]);                       \
    }                                                                           \
} while (0)

    // 4-stage ring, one barrier per slab (R9-proven schedule):
    // issue load s+2 -> wait_group(2) retires group s -> barrier -> compute s.
    // A one-barrier-lagging warp reads stages (s-1)&3 / s&3, never (s+2)&3.
    GEN_LOAD(0, 0);
    GEN_LOAD(1, 1);
    for (int s = 0; s < 32; s++) {
        if (s + 2 < 32) GEN_LOAD(s + 2, (s + 2) & 3);
        else            CPCOMMIT();          // dummy group keeps wait count uniform
        CPWAIT(2);
        __syncthreads();
        GEN_COMP(s & 3);
    }

    // epilogue: +bias, clamp, fp16 split, natural [row][col] store
    const float* __restrict__ bias = z ? bo : bi;
    __half* __restrict__ Oh = g_Vhi[z];
    __half* __restrict__ Ol = g_Vlo[z];
#pragma unroll
    for (int mi = 0; mi < 2; mi++)
#pragma unroll
        for (int ni = 0; ni < 8; ni++) {
            int rr = row0 + wm * 32 + mi * 16 + (lane >> 2);
            int gc = col0 + wn * 64 + ni * 8 + (lane & 3) * 2;
            float b0v = __ldg(bias + gc), b1v = __ldg(bias + gc + 1);

            float v0 = clamp5(acc[mi][ni][0] + b0v);
            float v1 = clamp5(acc[mi][ni][1] + b1v);
            __half h0 = __float2half_rn(v0), h1 = __float2half_rn(v1);
            *(__half2*)(Oh + (size_t)rr * NC + gc) = __halves2half2(h0, h1);
            *(__half2*)(Ol + (size_t)rr * NC + gc) =
                __halves2half2(__float2half_rn(v0 - __half2float(h0)),
                               __float2half_rn(v1 - __half2float(h1)));

            float v2 = clamp5(acc[mi][ni][2] + b0v);
            float v3 = clamp5(acc[mi][ni][3] + b1v);
            __half h2 = __float2half_rn(v2), h3 = __float2half_rn(v3);
            *(__half2*)(Oh + (size_t)(rr + 8) * NC + gc) = __halves2half2(h2, h3);
            *(__half2*)(Ol + (size_t)(rr + 8) * NC + gc) =
                __halves2half2(__float2half_rn(v2 - __half2float(h2)),
                               __float2half_rn(v3 - __half2float(h3)));
        }
#undef GEN_LOAD
#undef GEN_COMP
}

// ===========================================================================
// Phase 2: out[b] = wp[b] + iv[b]^T @ ov[b].  Per batch M=N=2048, K=128.
// K=128 = 4 slabs: ALL 4 stages + the 64KB wp tile loaded up-front via
// cp.async; MMAs run back-to-back with descending wait_group; epilogue
// reads wp from smem. Fragments hoisted per slab as in k_gen.
// SMEM: 4 stages x 34816 + wp 128 x 528B = 206848 B.
// ===========================================================================
#define P2_STAGE   34816
#define P2_PLANE   8704
#define P2_WPOFF   (4 * P2_STAGE)          // 139264
#define P2_WPROW   528                     // 128*4 + 16 pad
#define P2_SMEM    (P2_WPOFF + 128 * P2_WPROW)   // 206848

__global__ __launch_bounds__(256, 1)
void k_outer(const float* __restrict__ wp, float* __restrict__ out)
{
    extern __shared__ char smem[];
    const uint32_t sbase = smem_to_u32(smem);
    const int tid = threadIdx.x, lane = tid & 31, wid = tid >> 5;
    const int wm = wid & 3, wn = wid >> 2;
    const int b = blockIdx.z;
    const int i0 = blockIdx.y * 128, j0 = blockIdx.x * 128;

    const __half* __restrict__ pAh = g_Vhi[0] + (size_t)(b * 128) * NC + i0;
    const __half* __restrict__ pAl = g_Vlo[0] + (size_t)(b * 128) * NC + i0;
    const __half* __restrict__ pBh = g_Vhi[1] + (size_t)(b * 128) * NC + j0;
    const __half* __restrict__ pBl = g_Vlo[1] + (size_t)(b * 128) * NC + j0;

    float acc[2][8][4];
#pragma unroll
    for (int mi = 0; mi < 2; mi++)
#pragma unroll
        for (int ni = 0; ni < 8; ni++)
#pragma unroll
            for (int q = 0; q < 4; q++) acc[mi][ni][q] = 0.0f;

#define OUT_LOAD(s_) do {                                                       \
    const int d0_ = (s_) * 32;                                                  \
    const uint32_t b0_ = sbase + (uint32_t)(s_) * P2_STAGE;                     \
    _Pragma("unroll")                                                           \
    for (int i_ = 0; i_ < 8; i_++) {                                            \
        const int p_ = i_ >> 1;                                                 \
        const int cc_ = tid + (i_ & 1) * 256;                                   \
        const int row_ = cc_ >> 4, ch_ = cc_ & 15;                              \
        const uint32_t d_ = b0_ + p_ * P2_PLANE + row_ * 272 + ch_ * 16;        \
        const __half* g_ =                                                      \
            (p_ == 0 ? pAh : p_ == 1 ? pAl : p_ == 2 ? pBh : pBl)               \
            + (size_t)(d0_ + row_) * NC + ch_ * 8;                              \
        CPA16(d_, g_);                                                          \
    }                                                                           \
    CPCOMMIT();                                                                 \
} while (0)

#define OUT_COMP(st_) do {                                                      \
    const uint32_t sb_ = sbase + (uint32_t)(st_) * P2_STAGE;                    \
    uint32_t ah[2][2][4], al[2][2][4], bh[2][8][2], bl[2][8][2];                \
    _Pragma("unroll")                                                           \
    for (int ks = 0; ks < 2; ks++) {                                            \
        _Pragma("unroll")                                                       \
        for (int mi = 0; mi < 2; mi++) {                                        \
            uint32_t ra = sb_                                                   \
                + ((ks * 16 + ((lane >> 4) << 3) + (lane & 7)) * 136            \
                   + wm * 32 + mi * 16 + (((lane >> 3) & 1) << 3)) * 2;         \
            LDSM4T(ah[ks][mi][0], ah[ks][mi][1], ah[ks][mi][2], ah[ks][mi][3],  \
                   ra);                                                         \
            LDSM4T(al[ks][mi][0], al[ks][mi][1], al[ks][mi][2], al[ks][mi][3],  \
                   ra + P2_PLANE);                                              \
        }                                                                       \
        _Pragma("unroll")                                                       \
        for (int ng = 0; ng < 4; ng++) {                                        \
            uint32_t rb = sb_ + 2 * P2_PLANE                                    \
                + ((ks * 16 + (((lane >> 3) & 1) << 3) + (lane & 7)) * 136      \
                   + wn * 64 + ng * 16 + ((lane >> 4) << 3)) * 2;               \
            LDSM4T(bh[ks][2*ng][0], bh[ks][2*ng][1],                            \
                   bh[ks][2*ng+1][0], bh[ks][2*ng+1][1], rb);                   \
            LDSM4T(bl[ks][2*ng][0], bl[ks][2*ng][1],                            \
                   bl[ks][2*ng+1][0], bl[ks][2*ng+1][1], rb + P2_PLANE);        \
        }                                                                       \
    }                                                                           \
    _Pragma("unroll")                                                           \
    for (int ks = 0; ks < 2; ks++) {                                            \
        _Pragma("unroll")                                                       \
        for (int mi = 0; mi < 2; mi++)                                          \
            _Pragma("unroll")                                                   \
            for (int ni = 0; ni < 8; ni++)                                      \
                MMA(acc[mi][ni], ah[ks][mi], bh[ks][ni]);                       \
        _Pragma("unroll")                                                       \
        for (int mi = 0; mi < 2; mi++)                                          \
            _Pragma("unroll")                                                   \
            for (int ni = 0; ni < 8; ni++)                                      \
                MMA(acc[mi][ni], ah[ks][mi], bl[ks][ni]);                       \
        _Pragma("unroll")                                                       \
        for (int mi = 0; mi < 2; mi++)                                          \
            _Pragma("unroll")                                                   \
            for (int ni = 0; ni < 8; ni++)                                      \
                MMA(acc[mi][ni], al[ks][mi], bh[ks][ni]);                       \
    }                                                                           \
} while (0)

    // Issue everything: 4 data slabs (groups 0-3) + wp tile (group 4).
    OUT_LOAD(0);
    OUT_LOAD(1);
    OUT_LOAD(2);
    OUT_LOAD(3);
    {
        const float* wpp = wp + ((size_t)b * NC + i0) * NC + j0;
#pragma unroll
        for (int i_ = 0; i_ < 16; i_++) {
            int idx = tid + i_ * 256;          // 4096 uint4 total
            int row = idx >> 5, colq = idx & 31;
            uint32_t d_ = sbase + P2_WPOFF + row * P2_WPROW + colq * 16;
            CPA16(d_, wpp + (size_t)row * NC + colq * 4);
        }
        CPCOMMIT();
    }

    CPWAIT(4); __syncthreads(); OUT_COMP(0);
    CPWAIT(3); __syncthreads(); OUT_COMP(1);
    CPWAIT(2); __syncthreads(); OUT_COMP(2);
    CPWAIT(1); __syncthreads(); OUT_COMP(3);
    CPWAIT(0); __syncthreads();                 // wp tile ready in smem

    // epilogue: + weight_params (from smem), fp32 store
#pragma unroll
    for (int mi = 0; mi < 2; mi++)
#pragma unroll
        for (int ni = 0; ni < 8; ni++) {
            int rl = wm * 32 + mi * 16 + (lane >> 2);          // local row
            int cl = wn * 64 + ni * 8 + (lane & 3) * 2;        // local col
            float2 w0 = *(const float2*)(smem + P2_WPOFF + rl * P2_WPROW + cl * 4);
            float2 w1 = *(const float2*)(smem + P2_WPOFF + (rl + 8) * P2_WPROW + cl * 4);
            size_t g0 = ((size_t)b * NC + i0 + rl) * NC + j0 + cl;
            size_t g1 = g0 + (size_t)8 * NC;
            *(float2*)(out + g0) =
                make_float2(acc[mi][ni][0] + w0.x, acc[mi][ni][1] + w0.y);
            *(float2*)(out + g1) =
                make_float2(acc[mi][ni][2] + w1.x, acc[mi][ni][3] + w1.y);
        }
#undef OUT_LOAD
#undef OUT_COMP
}

// ---------------------------------------------------------------------------
// Launch
// ---------------------------------------------------------------------------
extern "C" void kernel_launch(void* const* d_in, const int* in_sizes, int n_in,
                              void* d_out, int out_size)
{
    const float* wp = (const float*)d_in[0];  // [16, 2048, 2048]
    const float* lg = (const float*)d_in[1];  // [16, 128, 1024]
    const float* Wi = (const float*)d_in[2];  // [1024, 2048]
    const float* bi = (const float*)d_in[3];  // [2048]
    const float* Wo = (const float*)d_in[4];  // [1024, 2048]
    const float* bo = (const float*)d_in[5];  // [2048]
    float* out = (float*)d_out;               // [16, 2048, 2048]

    cudaFuncSetAttribute(k_gen,
        cudaFuncAttributeMaxDynamicSharedMemorySize, 4 * P1_STAGE);
    cudaFuncSetAttribute(k_outer,
        cudaFuncAttributeMaxDynamicSharedMemorySize, P2_SMEM);

    k_split<<<(NROW * NK / 4 + 255) / 256, 256>>>(lg);
    k_wtrans<<<dim3(NC / 32, NK / 32), dim3(32, 8)>>>(Wi, 0);
    k_wtrans<<<dim3(NC / 32, NK / 32), dim3(32, 8)>>>(Wo, 1);

    k_gen<<<dim3(16, 16, 2), 256, 4 * P1_STAGE>>>(bi, bo);
    k_outer<<<dim3(16, 16, 16), 256, P2_SMEM>>>(wp, out);
}

// round 16
// speedup vs baseline: 1.7140x; 1.4443x over previous
#include <cuda_runtime.h>
#include <cuda_fp16.h>
#include <cstdint>

// Problem sizes
#define NROW 2048   // B*DEPTH = 16*128
#define NK   1024   // HID
#define NC   2048   // DIN == DOUT
#define B_   16

// ---------------------------------------------------------------------------
// fp16 split scratch (device globals).  A-operands split hi+lo; B-operands
// rounded to fp16 only (2-term scheme: C = (A_hi + A_lo) @ rn16(B)).
// ---------------------------------------------------------------------------
__device__ __align__(256) __half g_Lhi[NROW * NK], g_Llo[NROW * NK];   // logits split
__device__ __align__(256) __half g_Wthi[2][NC * NK];                   // W^T rounded
__device__ __align__(256) __half g_Vhi[2][NROW * NC];                  // iv(0)/ov(1) hi
__device__ __align__(256) __half g_Vlo[NROW * NC];                     // iv lo only

// ---------------------------------------------------------------------------
// helpers (all plain sm_80-era PTX — valid at target compute_103)
// ---------------------------------------------------------------------------
__device__ __forceinline__ uint32_t smem_to_u32(const void* p) {
    uint32_t a;
    asm("{ .reg .u64 t; cvta.to.shared.u64 t, %1; cvt.u32.u64 %0, t; }" : "=r"(a) : "l"(p));
    return a;
}

#define CPA16(s, g) \
    asm volatile("cp.async.cg.shared.global [%0], [%1], 16;" :: "r"(s), "l"(g))
#define CPCOMMIT() asm volatile("cp.async.commit_group;")
#define CPWAIT(n)  asm volatile("cp.async.wait_group %0;" :: "n"(n))

#define LDSM4(r0, r1, r2, r3, a) \
    asm volatile("ldmatrix.sync.aligned.m8n8.x4.shared.b16 {%0,%1,%2,%3}, [%4];" \
                 : "=r"(r0), "=r"(r1), "=r"(r2), "=r"(r3) : "r"(a))
#define LDSM4T(r0, r1, r2, r3, a) \
    asm volatile("ldmatrix.sync.aligned.m8n8.x4.trans.shared.b16 {%0,%1,%2,%3}, [%4];" \
                 : "=r"(r0), "=r"(r1), "=r"(r2), "=r"(r3) : "r"(a))

#define MMA(c, a, b) \
    asm volatile("mma.sync.aligned.m16n8k16.row.col.f32.f16.f16.f32 " \
                 "{%0,%1,%2,%3},{%4,%5,%6,%7},{%8,%9},{%0,%1,%2,%3};" \
                 : "+f"((c)[0]), "+f"((c)[1]), "+f"((c)[2]), "+f"((c)[3]) \
                 : "r"((a)[0]), "r"((a)[1]), "r"((a)[2]), "r"((a)[3]), \
                   "r"((b)[0]), "r"((b)[1]))

__device__ __forceinline__ float clamp5(float v) {
    return fminf(fmaxf(v, -5.0f), 5.0f);
}

// ---------------------------------------------------------------------------
// Prep 1: split logits fp32 -> fp16 hi/lo (same [row][k] layout)
// ---------------------------------------------------------------------------
__global__ void k_split(const float* __restrict__ X) {
    int i = blockIdx.x * blockDim.x + threadIdx.x;   // one float4 each
    if (i >= NROW * NK / 4) return;
    float4 v = reinterpret_cast<const float4*>(X)[i];
    __half h0 = __float2half_rn(v.x), h1 = __float2half_rn(v.y);
    __half h2 = __float2half_rn(v.z), h3 = __float2half_rn(v.w);
    __half2* H = reinterpret_cast<__half2*>(g_Lhi);
    __half2* L = reinterpret_cast<__half2*>(g_Llo);
    H[2 * i]     = __halves2half2(h0, h1);
    H[2 * i + 1] = __halves2half2(h2, h3);
    L[2 * i]     = __halves2half2(__float2half_rn(v.x - __half2float(h0)),
                                  __float2half_rn(v.y - __half2float(h1)));
    L[2 * i + 1] = __halves2half2(__float2half_rn(v.z - __half2float(h2)),
                                  __float2half_rn(v.w - __half2float(h3)));
}

// ---------------------------------------------------------------------------
// Prep 2: transpose + round W [1024 hid][2048 col] -> Wt[which] [col][hid]
// (hi plane only — B operand is single-rounded in the 2-term scheme)
// ---------------------------------------------------------------------------
__global__ void k_wtrans(const float* __restrict__ W, int which) {
    __shared__ float t[32][33];
    const int c0 = blockIdx.x * 32, h0 = blockIdx.y * 32;
    const int tx = threadIdx.x, ty = threadIdx.y;    // 32 x 8
#pragma unroll
    for (int j = 0; j < 4; j++)
        t[ty + j * 8][tx] = W[(size_t)(h0 + ty + j * 8) * NC + c0 + tx];
    __syncthreads();
    __half* hi = g_Wthi[which];
#pragma unroll
    for (int j = 0; j < 4; j++) {
        float v = t[tx][ty + j * 8];
        hi[(size_t)(c0 + ty + j * 8) * NK + h0 + tx] = __float2half_rn(v);
    }
}

// ===========================================================================
// Phase 1: V[z] = clamp(L @ Wt[z]^T + bias[z]).  M=2048, N=2048, K=1024.
// Block 128x128, BK=32, 8 warps (4m x 2n), 2-stage cp.async ring, 2 CTAs/SM.
// 2-term: acc += Ah*Bh; acc += Al*Bh  (64 MMAs/slab, was 96).
// SMEM stage: Ah|Al|Bh planes of [128][40] halves (pad 8) = 30720B.
// ===========================================================================
#define P1_PLANE 10240
#define P1_STAGE 30720

__global__ __launch_bounds__(256, 2)
void k_gen(const float* __restrict__ bi, const float* __restrict__ bo)
{
    extern __shared__ char smem[];
    const uint32_t sbase = smem_to_u32(smem);
    const int tid = threadIdx.x, lane = tid & 31, wid = tid >> 5;
    const int wm = wid & 3, wn = wid >> 2;
    const int row0 = blockIdx.y * 128, col0 = blockIdx.x * 128;
    const int z = blockIdx.z;

    const __half* __restrict__ pAh = g_Lhi + (size_t)row0 * NK;
    const __half* __restrict__ pAl = g_Llo + (size_t)row0 * NK;
    const __half* __restrict__ pBh = g_Wthi[z] + (size_t)col0 * NK;

    float acc[2][8][4];
#pragma unroll
    for (int mi = 0; mi < 2; mi++)
#pragma unroll
        for (int ni = 0; ni < 8; ni++)
#pragma unroll
            for (int q = 0; q < 4; q++) acc[mi][ni][q] = 0.0f;

#define GEN_LOAD(s_, st_) do {                                                  \
    const int k0_ = (s_) * 32;                                                  \
    const uint32_t d0_ = sbase + (uint32_t)(st_) * P1_STAGE;                    \
    _Pragma("unroll")                                                           \
    for (int i_ = 0; i_ < 6; i_++) {                                            \
        const int p_ = i_ >> 1;                                                 \
        const int cc_ = tid + (i_ & 1) * 256;                                   \
        const int row_ = cc_ >> 2, kc_ = cc_ & 3;                               \
        const uint32_t d_ = d0_ + p_ * P1_PLANE + row_ * 80 + kc_ * 16;         \
        const __half* g_ =                                                      \
            (p_ == 0 ? pAh : p_ == 1 ? pAl : pBh)                               \
            + (size_t)row_ * NK + k0_ + kc_ * 8;                                \
        CPA16(d_, g_);                                                          \
    }                                                                           \
    CPCOMMIT();                                                                 \
} while (0)

#define GEN_COMP(st_) do {                                                      \
    const uint32_t sb_ = sbase + (uint32_t)(st_) * P1_STAGE;                    \
    _Pragma("unroll")                                                           \
    for (int ks = 0; ks < 2; ks++) {                                            \
        uint32_t ah[2][4], al[2][4];                                            \
        _Pragma("unroll")                                                       \
        for (int mi = 0; mi < 2; mi++) {                                        \
            uint32_t ra = sb_ + ((wm * 32 + mi * 16 + (lane & 15)) * 40         \
                                 + ks * 16 + ((lane >> 4) << 3)) * 2;           \
            LDSM4(ah[mi][0], ah[mi][1], ah[mi][2], ah[mi][3], ra);              \
            LDSM4(al[mi][0], al[mi][1], al[mi][2], al[mi][3], ra + P1_PLANE);   \
        }                                                                       \
        _Pragma("unroll")                                                       \
        for (int ng = 0; ng < 4; ng++) {                                        \
            uint32_t bh[2][2];                                                  \
            uint32_t rb = sb_ + 2 * P1_PLANE                                    \
                + ((wn * 64 + ng * 16 + ((lane >> 4) << 3) + (lane & 7)) * 40   \
                   + ks * 16 + (((lane >> 3) & 1) << 3)) * 2;                   \
            LDSM4(bh[0][0], bh[0][1], bh[1][0], bh[1][1], rb);                  \
            _Pragma("unroll")                                                   \
            for (int mi = 0; mi < 2; mi++)                                      \
                _Pragma("unroll")                                               \
                for (int nn = 0; nn < 2; nn++)                                  \
                    MMA(acc[mi][2 * ng + nn], ah[mi], bh[nn]);                  \
            _Pragma("unroll")                                                   \
            for (int mi = 0; mi < 2; mi++)                                      \
                _Pragma("unroll")                                               \
                for (int nn = 0; nn < 2; nn++)                                  \
                    MMA(acc[mi][2 * ng + nn], al[mi], bh[nn]);                  \
        }                                                                       \
    }                                                                           \
} while (0)

    // 2-stage ring, two barriers per slab; co-resident CTA hides the stalls.
    GEN_LOAD(0, 0);
    for (int s = 0; s < 32; s++) {
        if (s + 1 < 32) { GEN_LOAD(s + 1, (s + 1) & 1); CPWAIT(1); }
        else            { CPWAIT(0); }
        __syncthreads();
        GEN_COMP(s & 1);
        __syncthreads();
    }

    // epilogue: +bias, clamp, store.  iv (z=0): fp16 hi+lo.  ov (z=1): hi only
    // (ov is the rounded B operand of phase 2 — its fp16 rounding IS the scheme).
    const float* __restrict__ bias = z ? bo : bi;
    __half* __restrict__ Oh = g_Vhi[z];
#pragma unroll
    for (int mi = 0; mi < 2; mi++)
#pragma unroll
        for (int ni = 0; ni < 8; ni++) {
            int rr = row0 + wm * 32 + mi * 16 + (lane >> 2);
            int gc = col0 + wn * 64 + ni * 8 + (lane & 3) * 2;
            float b0v = __ldg(bias + gc), b1v = __ldg(bias + gc + 1);

            float v0 = clamp5(acc[mi][ni][0] + b0v);
            float v1 = clamp5(acc[mi][ni][1] + b1v);
            __half h0 = __float2half_rn(v0), h1 = __float2half_rn(v1);
            *(__half2*)(Oh + (size_t)rr * NC + gc) = __halves2half2(h0, h1);

            float v2 = clamp5(acc[mi][ni][2] + b0v);
            float v3 = clamp5(acc[mi][ni][3] + b1v);
            __half h2 = __float2half_rn(v2), h3 = __float2half_rn(v3);
            *(__half2*)(Oh + (size_t)(rr + 8) * NC + gc) = __halves2half2(h2, h3);

            if (z == 0) {
                *(__half2*)(g_Vlo + (size_t)rr * NC + gc) =
                    __halves2half2(__float2half_rn(v0 - __half2float(h0)),
                                   __float2half_rn(v1 - __half2float(h1)));
                *(__half2*)(g_Vlo + (size_t)(rr + 8) * NC + gc) =
                    __halves2half2(__float2half_rn(v2 - __half2float(h2)),
                                   __float2half_rn(v3 - __half2float(h3)));
            }
        }
#undef GEN_LOAD
#undef GEN_COMP
}

// ===========================================================================
// Phase 2: out[b] = wp[b] + iv[b]^T @ ov[b].  Per batch M=N=2048, K=128.
// 2-stage ring, 2 CTAs/SM.  A = iv (hi+lo, split), B = ov (hi only).
// wp read straight from global in the epilogue (co-resident CTA overlaps).
// SMEM stage: Ah|Al|Bh planes of [32 d][136] halves (pad 8) = 26112B.
// ===========================================================================
#define P2_PLANE 8704
#define P2_STAGE 26112

__global__ __launch_bounds__(256, 2)
void k_outer(const float* __restrict__ wp, float* __restrict__ out)
{
    extern __shared__ char smem[];
    const uint32_t sbase = smem_to_u32(smem);
    const int tid = threadIdx.x, lane = tid & 31, wid = tid >> 5;
    const int wm = wid & 3, wn = wid >> 2;
    const int b = blockIdx.z;
    const int i0 = blockIdx.y * 128, j0 = blockIdx.x * 128;

    const __half* __restrict__ pAh = g_Vhi[0] + (size_t)(b * 128) * NC + i0;
    const __half* __restrict__ pAl = g_Vlo    + (size_t)(b * 128) * NC + i0;
    const __half* __restrict__ pBh = g_Vhi[1] + (size_t)(b * 128) * NC + j0;

    float acc[2][8][4];
#pragma unroll
    for (int mi = 0; mi < 2; mi++)
#pragma unroll
        for (int ni = 0; ni < 8; ni++)
#pragma unroll
            for (int q = 0; q < 4; q++) acc[mi][ni][q] = 0.0f;

#define OUT_LOAD(s_, st_) do {                                                  \
    const int d0_ = (s_) * 32;                                                  \
    const uint32_t b0_ = sbase + (uint32_t)(st_) * P2_STAGE;                    \
    _Pragma("unroll")                                                           \
    for (int i_ = 0; i_ < 6; i_++) {                                            \
        const int p_ = i_ >> 1;                                                 \
        const int cc_ = tid + (i_ & 1) * 256;                                   \
        const int row_ = cc_ >> 4, ch_ = cc_ & 15;                              \
        const uint32_t d_ = b0_ + p_ * P2_PLANE + row_ * 272 + ch_ * 16;        \
        const __half* g_ =                                                      \
            (p_ == 0 ? pAh : p_ == 1 ? pAl : pBh)                               \
            + (size_t)(d0_ + row_) * NC + ch_ * 8;                              \
        CPA16(d_, g_);                                                          \
    }                                                                           \
    CPCOMMIT();                                                                 \
} while (0)

#define OUT_COMP(st_) do {                                                      \
    const uint32_t sb_ = sbase + (uint32_t)(st_) * P2_STAGE;                    \
    _Pragma("unroll")                                                           \
    for (int ks = 0; ks < 2; ks++) {                                            \
        uint32_t ah[2][4], al[2][4];                                            \
        _Pragma("unroll")                                                       \
        for (int mi = 0; mi < 2; mi++) {                                        \
            uint32_t ra = sb_                                                   \
                + ((ks * 16 + ((lane >> 4) << 3) + (lane & 7)) * 136            \
                   + wm * 32 + mi * 16 + (((lane >> 3) & 1) << 3)) * 2;         \
            LDSM4T(ah[mi][0], ah[mi][1], ah[mi][2], ah[mi][3], ra);             \
            LDSM4T(al[mi][0], al[mi][1], al[mi][2], al[mi][3], ra + P2_PLANE);  \
        }                                                                       \
        _Pragma("unroll")                                                       \
        for (int ng = 0; ng < 4; ng++) {                                        \
            uint32_t bh[2][2];                                                  \
            uint32_t rb = sb_ + 2 * P2_PLANE                                    \
                + ((ks * 16 + (((lane >> 3) & 1) << 3) + (lane & 7)) * 136      \
                   + wn * 64 + ng * 16 + ((lane >> 4) << 3)) * 2;               \
            LDSM4T(bh[0][0], bh[0][1], bh[1][0], bh[1][1], rb);                 \
            _Pragma("unroll")                                                   \
            for (int mi = 0; mi < 2; mi++)                                      \
                _Pragma("unroll")                                               \
                for (int nn = 0; nn < 2; nn++)                                  \
                    MMA(acc[mi][2 * ng + nn], ah[mi], bh[nn]);                  \
            _Pragma("unroll")                                                   \
            for (int mi = 0; mi < 2; mi++)                                      \
                _Pragma("unroll")                                               \
                for (int nn = 0; nn < 2; nn++)                                  \
                    MMA(acc[mi][2 * ng + nn], al[mi], bh[nn]);                  \
        }                                                                       \
    }                                                                           \
} while (0)

    OUT_LOAD(0, 0);
    for (int s = 0; s < 4; s++) {
        if (s + 1 < 4) { OUT_LOAD(s + 1, (s + 1) & 1); CPWAIT(1); }
        else           { CPWAIT(0); }
        __syncthreads();
        OUT_COMP(s & 1);
        __syncthreads();
    }

    // epilogue: + weight_params (global; overlapped by co-resident CTA), store
#pragma unroll
    for (int mi = 0; mi < 2; mi++)
#pragma unroll
        for (int ni = 0; ni < 8; ni++) {
            int rr = i0 + wm * 32 + mi * 16 + (lane >> 2);
            int cc = j0 + wn * 64 + ni * 8 + (lane & 3) * 2;
            size_t g0 = ((size_t)b * NC + rr) * NC + cc;
            size_t g1 = g0 + (size_t)8 * NC;
            float2 w0 = *(const float2*)(wp + g0);
            float2 w1 = *(const float2*)(wp + g1);
            *(float2*)(out + g0) =
                make_float2(acc[mi][ni][0] + w0.x, acc[mi][ni][1] + w0.y);
            *(float2*)(out + g1) =
                make_float2(acc[mi][ni][2] + w1.x, acc[mi][ni][3] + w1.y);
        }
#undef OUT_LOAD
#undef OUT_COMP
}

// ---------------------------------------------------------------------------
// Launch
// ---------------------------------------------------------------------------
extern "C" void kernel_launch(void* const* d_in, const int* in_sizes, int n_in,
                              void* d_out, int out_size)
{
    const float* wp = (const float*)d_in[0];  // [16, 2048, 2048]
    const float* lg = (const float*)d_in[1];  // [16, 128, 1024]
    const float* Wi = (const float*)d_in[2];  // [1024, 2048]
    const float* bi = (const float*)d_in[3];  // [2048]
    const float* Wo = (const float*)d_in[4];  // [1024, 2048]
    const float* bo = (const float*)d_in[5];  // [2048]
    float* out = (float*)d_out;               // [16, 2048, 2048]

    cudaFuncSetAttribute(k_gen,
        cudaFuncAttributeMaxDynamicSharedMemorySize, 2 * P1_STAGE);
    cudaFuncSetAttribute(k_outer,
        cudaFuncAttributeMaxDynamicSharedMemorySize, 2 * P2_STAGE);

    k_split<<<(NROW * NK / 4 + 255) / 256, 256>>>(lg);
    k_wtrans<<<dim3(NC / 32, NK / 32), dim3(32, 8)>>>(Wi, 0);
    k_wtrans<<<dim3(NC / 32, NK / 32), dim3(32, 8)>>>(Wo, 1);

    k_gen<<<dim3(16, 16, 2), 256, 2 * P1_STAGE>>>(bi, bo);
    k_outer<<<dim3(16, 16, 16), 256, 2 * P2_STAGE>>>(wp, out);
}

// round 17
// speedup vs baseline: 1.8053x; 1.0532x over previous
#include <cuda_runtime.h>
#include <cuda_fp16.h>
#include <cstdint>

// Problem sizes
#define NROW 2048   // B*DEPTH = 16*128
#define NK   1024   // HID
#define NC   2048   // DIN == DOUT
#define B_   16

// ---------------------------------------------------------------------------
// fp16 split scratch.  Phase 1 (2-term): A = logits hi+lo, B = rn16(W^T).
// Phase 2 (1-term): A = rn16(iv), B = rn16(ov) — both hi-only.
// ---------------------------------------------------------------------------
__device__ __align__(256) __half g_Lhi[NROW * NK], g_Llo[NROW * NK];   // logits split
__device__ __align__(256) __half g_Wthi[2][NC * NK];                   // W^T rounded
__device__ __align__(256) __half g_Vhi[2][NROW * NC];                  // iv(0)/ov(1) hi

// ---------------------------------------------------------------------------
// helpers (all plain sm_80-era PTX — valid at target compute_103)
// ---------------------------------------------------------------------------
__device__ __forceinline__ uint32_t smem_to_u32(const void* p) {
    uint32_t a;
    asm("{ .reg .u64 t; cvta.to.shared.u64 t, %1; cvt.u32.u64 %0, t; }" : "=r"(a) : "l"(p));
    return a;
}

#define CPA16(s, g) \
    asm volatile("cp.async.cg.shared.global [%0], [%1], 16;" :: "r"(s), "l"(g))
#define CPCOMMIT() asm volatile("cp.async.commit_group;")
#define CPWAIT(n)  asm volatile("cp.async.wait_group %0;" :: "n"(n))

#define LDSM4(r0, r1, r2, r3, a) \
    asm volatile("ldmatrix.sync.aligned.m8n8.x4.shared.b16 {%0,%1,%2,%3}, [%4];" \
                 : "=r"(r0), "=r"(r1), "=r"(r2), "=r"(r3) : "r"(a))
#define LDSM4T(r0, r1, r2, r3, a) \
    asm volatile("ldmatrix.sync.aligned.m8n8.x4.trans.shared.b16 {%0,%1,%2,%3}, [%4];" \
                 : "=r"(r0), "=r"(r1), "=r"(r2), "=r"(r3) : "r"(a))

#define MMA(c, a, b) \
    asm volatile("mma.sync.aligned.m16n8k16.row.col.f32.f16.f16.f32 " \
                 "{%0,%1,%2,%3},{%4,%5,%6,%7},{%8,%9},{%0,%1,%2,%3};" \
                 : "+f"((c)[0]), "+f"((c)[1]), "+f"((c)[2]), "+f"((c)[3]) \
                 : "r"((a)[0]), "r"((a)[1]), "r"((a)[2]), "r"((a)[3]), \
                   "r"((b)[0]), "r"((b)[1]))

__device__ __forceinline__ float clamp5(float v) {
    return fminf(fmaxf(v, -5.0f), 5.0f);
}

// ---------------------------------------------------------------------------
// Prep 1: split logits fp32 -> fp16 hi/lo (same [row][k] layout)
// ---------------------------------------------------------------------------
__global__ void k_split(const float* __restrict__ X) {
    int i = blockIdx.x * blockDim.x + threadIdx.x;   // one float4 each
    if (i >= NROW * NK / 4) return;
    float4 v = reinterpret_cast<const float4*>(X)[i];
    __half h0 = __float2half_rn(v.x), h1 = __float2half_rn(v.y);
    __half h2 = __float2half_rn(v.z), h3 = __float2half_rn(v.w);
    __half2* H = reinterpret_cast<__half2*>(g_Lhi);
    __half2* L = reinterpret_cast<__half2*>(g_Llo);
    H[2 * i]     = __halves2half2(h0, h1);
    H[2 * i + 1] = __halves2half2(h2, h3);
    L[2 * i]     = __halves2half2(__float2half_rn(v.x - __half2float(h0)),
                                  __float2half_rn(v.y - __half2float(h1)));
    L[2 * i + 1] = __halves2half2(__float2half_rn(v.z - __half2float(h2)),
                                  __float2half_rn(v.w - __half2float(h3)));
}

// ---------------------------------------------------------------------------
// Prep 2: transpose + round W [1024 hid][2048 col] -> Wt[which] [col][hid]
// ---------------------------------------------------------------------------
__global__ void k_wtrans(const float* __restrict__ W, int which) {
    __shared__ float t[32][33];
    const int c0 = blockIdx.x * 32, h0 = blockIdx.y * 32;
    const int tx = threadIdx.x, ty = threadIdx.y;    // 32 x 8
#pragma unroll
    for (int j = 0; j < 4; j++)
        t[ty + j * 8][tx] = W[(size_t)(h0 + ty + j * 8) * NC + c0 + tx];
    __syncthreads();
    __half* hi = g_Wthi[which];
#pragma unroll
    for (int j = 0; j < 4; j++) {
        float v = t[tx][ty + j * 8];
        hi[(size_t)(c0 + ty + j * 8) * NK + h0 + tx] = __float2half_rn(v);
    }
}

// ===========================================================================
// Phase 1: V[z] = clamp(L @ Wt[z]^T + bias[z]).  M=2048, N=2048, K=1024.
// Block 128x128, BK=32, 8 warps (4m x 2n), 2-stage cp.async ring, 2 CTAs/SM.
// 2-term: acc += Ah*Bh; acc += Al*Bh.  Output stored fp16 hi only (phase-2
// consumes it rounded anyway).
// SMEM stage: Ah|Al|Bh planes of [128][40] halves (pad 8) = 30720B.
// ===========================================================================
#define P1_PLANE 10240
#define P1_STAGE 30720

__global__ __launch_bounds__(256, 2)
void k_gen(const float* __restrict__ bi, const float* __restrict__ bo)
{
    extern __shared__ char smem[];
    const uint32_t sbase = smem_to_u32(smem);
    const int tid = threadIdx.x, lane = tid & 31, wid = tid >> 5;
    const int wm = wid & 3, wn = wid >> 2;
    const int row0 = blockIdx.y * 128, col0 = blockIdx.x * 128;
    const int z = blockIdx.z;

    const __half* __restrict__ pAh = g_Lhi + (size_t)row0 * NK;
    const __half* __restrict__ pAl = g_Llo + (size_t)row0 * NK;
    const __half* __restrict__ pBh = g_Wthi[z] + (size_t)col0 * NK;

    float acc[2][8][4];
#pragma unroll
    for (int mi = 0; mi < 2; mi++)
#pragma unroll
        for (int ni = 0; ni < 8; ni++)
#pragma unroll
            for (int q = 0; q < 4; q++) acc[mi][ni][q] = 0.0f;

#define GEN_LOAD(s_, st_) do {                                                  \
    const int k0_ = (s_) * 32;                                                  \
    const uint32_t d0_ = sbase + (uint32_t)(st_) * P1_STAGE;                    \
    _Pragma("unroll")                                                           \
    for (int i_ = 0; i_ < 6; i_++) {                                            \
        const int p_ = i_ >> 1;                                                 \
        const int cc_ = tid + (i_ & 1) * 256;                                   \
        const int row_ = cc_ >> 2, kc_ = cc_ & 3;                               \
        const uint32_t d_ = d0_ + p_ * P1_PLANE + row_ * 80 + kc_ * 16;         \
        const __half* g_ =                                                      \
            (p_ == 0 ? pAh : p_ == 1 ? pAl : pBh)                               \
            + (size_t)row_ * NK + k0_ + kc_ * 8;                                \
        CPA16(d_, g_);                                                          \
    }                                                                           \
    CPCOMMIT();                                                                 \
} while (0)

#define GEN_COMP(st_) do {                                                      \
    const uint32_t sb_ = sbase + (uint32_t)(st_) * P1_STAGE;                    \
    _Pragma("unroll")                                                           \
    for (int ks = 0; ks < 2; ks++) {                                            \
        uint32_t ah[2][4], al[2][4];                                            \
        _Pragma("unroll")                                                       \
        for (int mi = 0; mi < 2; mi++) {                                        \
            uint32_t ra = sb_ + ((wm * 32 + mi * 16 + (lane & 15)) * 40         \
                                 + ks * 16 + ((lane >> 4) << 3)) * 2;           \
            LDSM4(ah[mi][0], ah[mi][1], ah[mi][2], ah[mi][3], ra);              \
            LDSM4(al[mi][0], al[mi][1], al[mi][2], al[mi][3], ra + P1_PLANE);   \
        }                                                                       \
        _Pragma("unroll")                                                       \
        for (int ng = 0; ng < 4; ng++) {                                        \
            uint32_t bh[2][2];                                                  \
            uint32_t rb = sb_ + 2 * P1_PLANE                                    \
                + ((wn * 64 + ng * 16 + ((lane >> 4) << 3) + (lane & 7)) * 40   \
                   + ks * 16 + (((lane >> 3) & 1) << 3)) * 2;                   \
            LDSM4(bh[0][0], bh[0][1], bh[1][0], bh[1][1], rb);                  \
            _Pragma("unroll")                                                   \
            for (int mi = 0; mi < 2; mi++)                                      \
                _Pragma("unroll")                                               \
                for (int nn = 0; nn < 2; nn++)                                  \
                    MMA(acc[mi][2 * ng + nn], ah[mi], bh[nn]);                  \
            _Pragma("unroll")                                                   \
            for (int mi = 0; mi < 2; mi++)                                      \
                _Pragma("unroll")                                               \
                for (int nn = 0; nn < 2; nn++)                                  \
                    MMA(acc[mi][2 * ng + nn], al[mi], bh[nn]);                  \
        }                                                                       \
    }                                                                           \
} while (0)

    GEN_LOAD(0, 0);
    for (int s = 0; s < 32; s++) {
        if (s + 1 < 32) { GEN_LOAD(s + 1, (s + 1) & 1); CPWAIT(1); }
        else            { CPWAIT(0); }
        __syncthreads();
        GEN_COMP(s & 1);
        __syncthreads();
    }

    // epilogue: +bias, clamp, fp16 hi-only store
    const float* __restrict__ bias = z ? bo : bi;
    __half* __restrict__ Oh = g_Vhi[z];
#pragma unroll
    for (int mi = 0; mi < 2; mi++)
#pragma unroll
        for (int ni = 0; ni < 8; ni++) {
            int rr = row0 + wm * 32 + mi * 16 + (lane >> 2);
            int gc = col0 + wn * 64 + ni * 8 + (lane & 3) * 2;
            float b0v = __ldg(bias + gc), b1v = __ldg(bias + gc + 1);

            float v0 = clamp5(acc[mi][ni][0] + b0v);
            float v1 = clamp5(acc[mi][ni][1] + b1v);
            *(__half2*)(Oh + (size_t)rr * NC + gc) =
                __halves2half2(__float2half_rn(v0), __float2half_rn(v1));

            float v2 = clamp5(acc[mi][ni][2] + b0v);
            float v3 = clamp5(acc[mi][ni][3] + b1v);
            *(__half2*)(Oh + (size_t)(rr + 8) * NC + gc) =
                __halves2half2(__float2half_rn(v2), __float2half_rn(v3));
        }
#undef GEN_LOAD
#undef GEN_COMP
}

// ===========================================================================
// Phase 2: out[b] = wp[b] + iv[b]^T @ ov[b].  Per batch M=N=2048, K=128.
// SINGLE-TERM: A = rn16(iv), B = rn16(ov).  16 MMAs per k16-step per warp.
// DRAM (wp+out, 512MB) is now the binder; 2-stage ring, 2 CTAs/SM.
// SMEM stage: Ah|Bh planes of [32 d][136] halves (pad 8) = 17408B.
// ===========================================================================
#define P2_PLANE 8704
#define P2_STAGE 17408

__global__ __launch_bounds__(256, 2)
void k_outer(const float* __restrict__ wp, float* __restrict__ out)
{
    extern __shared__ char smem[];
    const uint32_t sbase = smem_to_u32(smem);
    const int tid = threadIdx.x, lane = tid & 31, wid = tid >> 5;
    const int wm = wid & 3, wn = wid >> 2;
    const int b = blockIdx.z;
    const int i0 = blockIdx.y * 128, j0 = blockIdx.x * 128;

    const __half* __restrict__ pAh = g_Vhi[0] + (size_t)(b * 128) * NC + i0;
    const __half* __restrict__ pBh = g_Vhi[1] + (size_t)(b * 128) * NC + j0;

    float acc[2][8][4];
#pragma unroll
    for (int mi = 0; mi < 2; mi++)
#pragma unroll
        for (int ni = 0; ni < 8; ni++)
#pragma unroll
            for (int q = 0; q < 4; q++) acc[mi][ni][q] = 0.0f;

#define OUT_LOAD(s_, st_) do {                                                  \
    const int d0_ = (s_) * 32;                                                  \
    const uint32_t b0_ = sbase + (uint32_t)(st_) * P2_STAGE;                    \
    _Pragma("unroll")                                                           \
    for (int i_ = 0; i_ < 4; i_++) {                                            \
        const int p_ = i_ >> 1;                                                 \
        const int cc_ = tid + (i_ & 1) * 256;                                   \
        const int row_ = cc_ >> 4, ch_ = cc_ & 15;                              \
        const uint32_t d_ = b0_ + p_ * P2_PLANE + row_ * 272 + ch_ * 16;        \
        const __half* g_ = (p_ == 0 ? pAh : pBh)                                \
            + (size_t)(d0_ + row_) * NC + ch_ * 8;                              \
        CPA16(d_, g_);                                                          \
    }                                                                           \
    CPCOMMIT();                                                                 \
} while (0)

#define OUT_COMP(st_) do {                                                      \
    const uint32_t sb_ = sbase + (uint32_t)(st_) * P2_STAGE;                    \
    _Pragma("unroll")                                                           \
    for (int ks = 0; ks < 2; ks++) {                                            \
        uint32_t ah[2][4];                                                      \
        _Pragma("unroll")                                                       \
        for (int mi = 0; mi < 2; mi++) {                                        \
            uint32_t ra = sb_                                                   \
                + ((ks * 16 + ((lane >> 4) << 3) + (lane & 7)) * 136            \
                   + wm * 32 + mi * 16 + (((lane >> 3) & 1) << 3)) * 2;         \
            LDSM4T(ah[mi][0], ah[mi][1], ah[mi][2], ah[mi][3], ra);             \
        }                                                                       \
        _Pragma("unroll")                                                       \
        for (int ng = 0; ng < 4; ng++) {                                        \
            uint32_t bh[2][2];                                                  \
            uint32_t rb = sb_ + P2_PLANE                                        \
                + ((ks * 16 + (((lane >> 3) & 1) << 3) + (lane & 7)) * 136      \
                   + wn * 64 + ng * 16 + ((lane >> 4) << 3)) * 2;               \
            LDSM4T(bh[0][0], bh[0][1], bh[1][0], bh[1][1], rb);                 \
            _Pragma("unroll")                                                   \
            for (int mi = 0; mi < 2; mi++)                                      \
                _Pragma("unroll")                                               \
                for (int nn = 0; nn < 2; nn++)                                  \
                    MMA(acc[mi][2 * ng + nn], ah[mi], bh[nn]);                  \
        }                                                                       \
    }                                                                           \
} while (0)

    OUT_LOAD(0, 0);
    for (int s = 0; s < 4; s++) {
        if (s + 1 < 4) { OUT_LOAD(s + 1, (s + 1) & 1); CPWAIT(1); }
        else           { CPWAIT(0); }
        __syncthreads();
        OUT_COMP(s & 1);
        __syncthreads();
    }

    // epilogue: + weight_params (global; overlapped by co-resident CTA), store
#pragma unroll
    for (int mi = 0; mi < 2; mi++)
#pragma unroll
        for (int ni = 0; ni < 8; ni++) {
            int rr = i0 + wm * 32 + mi * 16 + (lane >> 2);
            int cc = j0 + wn * 64 + ni * 8 + (lane & 3) * 2;
            size_t g0 = ((size_t)b * NC + rr) * NC + cc;
            size_t g1 = g0 + (size_t)8 * NC;
            float2 w0 = *(const float2*)(wp + g0);
            float2 w1 = *(const float2*)(wp + g1);
            *(float2*)(out + g0) =
                make_float2(acc[mi][ni][0] + w0.x, acc[mi][ni][1] + w0.y);
            *(float2*)(out + g1) =
                make_float2(acc[mi][ni][2] + w1.x, acc[mi][ni][3] + w1.y);
        }
#undef OUT_LOAD
#undef OUT_COMP
}

// ---------------------------------------------------------------------------
// Launch
// ---------------------------------------------------------------------------
extern "C" void kernel_launch(void* const* d_in, const int* in_sizes, int n_in,
                              void* d_out, int out_size)
{
    const float* wp = (const float*)d_in[0];  // [16, 2048, 2048]
    const float* lg = (const float*)d_in[1];  // [16, 128, 1024]
    const float* Wi = (const float*)d_in[2];  // [1024, 2048]
    const float* bi = (const float*)d_in[3];  // [2048]
    const float* Wo = (const float*)d_in[4];  // [1024, 2048]
    const float* bo = (const float*)d_in[5];  // [2048]
    float* out = (float*)d_out;               // [16, 2048, 2048]

    cudaFuncSetAttribute(k_gen,
        cudaFuncAttributeMaxDynamicSharedMemorySize, 2 * P1_STAGE);
    cudaFuncSetAttribute(k_outer,
        cudaFuncAttributeMaxDynamicSharedMemorySize, 2 * P2_STAGE);

    k_split<<<(NROW * NK / 4 + 255) / 256, 256>>>(lg);
    k_wtrans<<<dim3(NC / 32, NK / 32), dim3(32, 8)>>>(Wi, 0);
    k_wtrans<<<dim3(NC / 32, NK / 32), dim3(32, 8)>>>(Wo, 1);

    k_gen<<<dim3(16, 16, 2), 256, 2 * P1_STAGE>>>(bi, bo);
    k_outer<<<dim3(16, 16, 16), 256, 2 * P2_STAGE>>>(wp, out);
}